// round 7
// baseline (speedup 1.0000x reference)
#include <cuda_runtime.h>
#include <cuda_bf16.h>
#include <cstdint>

#define NSMP   8192
#define NA     512
#define DOUT   256
#define PITCH  8712   // input row length
#define ACOL0  512    // A starts at input col 512
#define OPITCH 8448   // output row length

// Scratch (static device globals — no runtime allocation)
__device__ float g_part[64 * NSMP];
__device__ float g_dinv[NSMP];
__device__ __align__(16) __nv_bfloat16 g_supT[(size_t)DOUT * NSMP]; // S_T[n][j]
__device__ __align__(16) __nv_bfloat16 g_WT[(size_t)DOUT * NA];     // W^T[n][k] bf16

// ---------------------------------------------------------------------------
// PTX helpers (base-target-safe)
// ---------------------------------------------------------------------------
__device__ __forceinline__ uint32_t s2u(const void* p) {
    return (uint32_t)__cvta_generic_to_shared(p);
}
__device__ __forceinline__ void cp_async16(uint32_t s, const void* g) {
    asm volatile("cp.async.cg.shared.global [%0], [%1], 16;" :: "r"(s), "l"(g) : "memory");
}
__device__ __forceinline__ void cp_commit() {
    asm volatile("cp.async.commit_group;" ::: "memory");
}
template <int N>
__device__ __forceinline__ void cp_wait() {
    asm volatile("cp.async.wait_group %0;" :: "n"(N) : "memory");
}
__device__ __forceinline__ void ldsm4(uint32_t* r, uint32_t addr) {
    asm volatile("ldmatrix.sync.aligned.m8n8.x4.shared.b16 {%0,%1,%2,%3}, [%4];"
                 : "=r"(r[0]), "=r"(r[1]), "=r"(r[2]), "=r"(r[3]) : "r"(addr));
}
__device__ __forceinline__ void mma16816(float* d, const uint32_t* a, uint32_t b0, uint32_t b1) {
    asm volatile(
        "mma.sync.aligned.m16n8k16.row.col.f32.bf16.bf16.f32 "
        "{%0,%1,%2,%3}, {%4,%5,%6,%7}, {%8,%9}, {%0,%1,%2,%3};"
        : "+f"(d[0]), "+f"(d[1]), "+f"(d[2]), "+f"(d[3])
        : "r"(a[0]), "r"(a[1]), "r"(a[2]), "r"(a[3]), "r"(b0), "r"(b1));
}
// SW128-swizzled smem offset for (row, 16B-chunk c) with 128B rows
__device__ __forceinline__ uint32_t swz(int row, int c) {
    return (uint32_t)(row * 128 + ((c ^ (row & 7)) << 4));
}

// ---------------------------------------------------------------------------
// Kernel: W^T bf16 (tiny, independent)
// ---------------------------------------------------------------------------
__global__ void wt_kernel(const float* __restrict__ w) {
    __shared__ float ts[32][33];
    int k0 = blockIdx.x * 32, n0 = blockIdx.y * 32;
    int t = threadIdx.x;
    int a = t >> 5, b = t & 31;
    #pragma unroll
    for (int i = 0; i < 4; ++i)
        ts[a + 8 * i][b] = w[(size_t)(k0 + a + 8 * i) * DOUT + n0 + b];
    __syncthreads();
    #pragma unroll
    for (int i = 0; i < 4; ++i)
        g_WT[(size_t)(n0 + a + 8 * i) * NA + k0 + b] = __float2bfloat16(ts[b][a + 8 * i]);
}

// ---------------------------------------------------------------------------
// Kernel: partial column sums of A (float4, deterministic)
// ---------------------------------------------------------------------------
__global__ void colsum_part(const float* __restrict__ in) {
    int col = (blockIdx.x * 256 + threadIdx.x) * 4;
    int r0  = blockIdx.y * 128;
    const float* p = in + (size_t)r0 * PITCH + ACOL0 + col;
    float4 s = make_float4(0.f, 0.f, 0.f, 0.f);
    #pragma unroll 8
    for (int r = 0; r < 128; ++r) {
        float4 v = *(const float4*)p;
        s.x += v.x; s.y += v.y; s.z += v.z; s.w += v.w;
        p += PITCH;
    }
    *(float4*)(g_part + blockIdx.y * NSMP + col) = s;
}

__global__ void finalize_d() {
    int col = blockIdx.x * 256 + threadIdx.x;
    float s = 1.0f;
    #pragma unroll
    for (int i = 0; i < 64; ++i) s += g_part[i * NSMP + col];
    g_dinv[col] = rsqrtf(s);
}

// ---------------------------------------------------------------------------
// support (mma.sync): S_T[n][j] = bf16( dinv[j] * (X @ W)[j,n] )
// CTA 64x256, K=512, grid 128. (unchanged — 17.5 us)
// ---------------------------------------------------------------------------
#define SP_A0 0
#define SP_B0 8192
#define SP_A1 40960
#define SP_B1 49152
#define SP_TOTAL 81920
#define ST_PITCH 144

__device__ __forceinline__ void sp_load(const float* in, char* smem, int buf, int k0,
                                        int tid, int m0) {
    uint32_t bs = s2u(smem + (buf ? SP_B1 : SP_B0));
    const char* gB = (const char*)g_WT + (size_t)k0 * 2;
    #pragma unroll
    for (int c = 0; c < 8; ++c) {
        int chunk = tid + c * 256;
        int row = chunk >> 3;
        int seg = chunk & 7;
        cp_async16(bs + swz(row, seg), gB + (size_t)row * (NA * 2) + seg * 16);
    }
    cp_commit();
    char* As = smem + (buf ? SP_A1 : SP_A0);
    int f = tid & 15, r0 = tid >> 4;
    #pragma unroll
    for (int i = 0; i < 4; ++i) {
        int row = r0 + 16 * i;
        float4 v = *(const float4*)(in + (size_t)(m0 + row) * PITCH + k0 + f * 4);
        __nv_bfloat162 h0 = __floats2bfloat162_rn(v.x, v.y);
        __nv_bfloat162 h1 = __floats2bfloat162_rn(v.z, v.w);
        *(uint2*)(As + swz(row, f >> 1) + (f & 1) * 8) =
            make_uint2(*(uint32_t*)&h0, *(uint32_t*)&h1);
    }
}

__global__ void __launch_bounds__(256, 1) support_mma(const float* __restrict__ in) {
    extern __shared__ char smem[];
    int tid = threadIdx.x;
    int wid = tid >> 5, lane = tid & 31;
    int m0 = blockIdx.x * 64;
    int warp_m = (wid & 1) * 32;
    int warp_n = (wid >> 1) * 64;

    int rowA[2], rowB[4];
    #pragma unroll
    for (int mi = 0; mi < 2; ++mi) rowA[mi] = warp_m + mi * 16 + (lane & 15);
    int hiA = lane >> 4;
    #pragma unroll
    for (int nb = 0; nb < 4; ++nb)
        rowB[nb] = warp_n + nb * 16 + ((lane >> 4) << 3) + (lane & 7);
    int hiB = (lane >> 3) & 1;

    float acc[2][8][4] = {};

    sp_load(in, smem, 0, 0, tid, m0);
    for (int it = 0; it < NA / 64; ++it) {
        int buf = it & 1;
        if (it + 1 < NA / 64) { sp_load(in, smem, buf ^ 1, (it + 1) * 64, tid, m0); cp_wait<1>(); }
        else cp_wait<0>();
        __syncthreads();
        uint32_t As = s2u(smem + (buf ? SP_A1 : SP_A0));
        uint32_t Bs = s2u(smem + (buf ? SP_B1 : SP_B0));
        #pragma unroll
        for (int kk = 0; kk < 4; ++kk) {
            uint32_t a[2][4];
            #pragma unroll
            for (int mi = 0; mi < 2; ++mi)
                ldsm4(a[mi], As + swz(rowA[mi], kk * 2 + hiA));
            #pragma unroll
            for (int nb = 0; nb < 4; ++nb) {
                uint32_t b[4];
                ldsm4(b, Bs + swz(rowB[nb], kk * 2 + hiB));
                mma16816(acc[0][2 * nb],     a[0], b[0], b[1]);
                mma16816(acc[0][2 * nb + 1], a[0], b[2], b[3]);
                mma16816(acc[1][2 * nb],     a[1], b[0], b[1]);
                mma16816(acc[1][2 * nb + 1], a[1], b[2], b[3]);
            }
        }
        __syncthreads();
    }

    int qr = lane >> 2, qc = (lane & 3) * 2;
    #pragma unroll
    for (int mi = 0; mi < 2; ++mi) {
        int j0 = warp_m + mi * 16 + qr;
        float dv0 = g_dinv[m0 + j0];
        float dv1 = g_dinv[m0 + j0 + 8];
        #pragma unroll
        for (int n8 = 0; n8 < 8; ++n8) {
            int n = warp_n + n8 * 8 + qc;
            *(__nv_bfloat16*)(smem + n * ST_PITCH + j0 * 2)             = __float2bfloat16(dv0 * acc[mi][n8][0]);
            *(__nv_bfloat16*)(smem + (n + 1) * ST_PITCH + j0 * 2)       = __float2bfloat16(dv0 * acc[mi][n8][1]);
            *(__nv_bfloat16*)(smem + n * ST_PITCH + (j0 + 8) * 2)       = __float2bfloat16(dv1 * acc[mi][n8][2]);
            *(__nv_bfloat16*)(smem + (n + 1) * ST_PITCH + (j0 + 8) * 2) = __float2bfloat16(dv1 * acc[mi][n8][3]);
        }
    }
    __syncthreads();
    #pragma unroll
    for (int c = 0; c < 8; ++c) {
        int chunk = tid + c * 256;
        int n = chunk >> 3;
        int seg = chunk & 7;
        uint4 v = *(const uint4*)(smem + n * ST_PITCH + seg * 16);
        *(uint4*)((char*)g_supT + ((size_t)n * NSMP + m0) * 2 + seg * 16) = v;
    }
}

// ---------------------------------------------------------------------------
// main (mma.sync): out[:, :256] = diag(dinv) * (A+I) @ S ; out[:, 256:] = A+I
// CTA 64x256, grid 128, 3-stage ring, processA pipelined ONE AHEAD of mma.
// ---------------------------------------------------------------------------
#define MGS_STRIDE 49152   // per-stage: B(32KB) + Araw(16KB)
#define MGS_AOFF   32768
#define MG_AF      147456  // bf16 A, 2 x 8KB
#define MG3_TOTAL  163840
#define NIT        (NSMP / 64)

__device__ __forceinline__ void mg3_load(const float* in, char* smem, int stage, int k0,
                                         int tid, int m0) {
    uint32_t bs = s2u(smem + stage * MGS_STRIDE);
    const char* gB = (const char*)g_supT + (size_t)k0 * 2;
    #pragma unroll
    for (int c = 0; c < 8; ++c) {
        int chunk = tid + c * 256;
        int row = chunk >> 3;
        int seg = chunk & 7;
        cp_async16(bs + swz(row, seg), gB + (size_t)row * (NSMP * 2) + seg * 16);
    }
    uint32_t ar = s2u(smem + stage * MGS_STRIDE + MGS_AOFF);
    int r = tid >> 2, cb = tid & 3;
    const char* gA = (const char*)(in + (size_t)(m0 + r) * PITCH + ACOL0 + k0);
    #pragma unroll
    for (int i = 0; i < 4; ++i) {
        int ci = cb + 4 * i;
        cp_async16(ar + r * 256 + ((ci ^ (r & 15)) << 4), gA + ci * 16);
    }
    cp_commit();
}

__global__ void __launch_bounds__(256, 1) main_gemm4(const float* __restrict__ in,
                                                     float* __restrict__ out) {
    extern __shared__ char smem[];
    int tid = threadIdx.x;
    int wid = tid >> 5, lane = tid & 31;
    int m0 = blockIdx.x * 64;
    int warp_m = (wid & 1) * 32;
    int warp_n = (wid >> 1) * 64;

    int rowA[2], rowB[4];
    #pragma unroll
    for (int mi = 0; mi < 2; ++mi) rowA[mi] = warp_m + mi * 16 + (lane & 15);
    int hiA = lane >> 4;
    #pragma unroll
    for (int nb = 0; nb < 4; ++nb)
        rowB[nb] = warp_n + nb * 16 + ((lane >> 4) << 3) + (lane & 7);
    int hiB = (lane >> 3) & 1;

    float acc[2][8][4] = {};

    int pr = tid >> 2, pc = tid & 3;
    int grow = m0 + pr;
    float* aog = out + (size_t)grow * OPITCH + DOUT;

    // prologue: stage 0,1 in flight; processA(0) -> af0
    mg3_load(in, smem, 0, 0, tid, m0);
    mg3_load(in, smem, 1, 64, tid, m0);
    cp_wait<1>();
    __syncthreads();
    {
        const char* ar = smem + 0 * MGS_STRIDE + MGS_AOFF;
        char* af = smem + MG_AF;
        #pragma unroll
        for (int i = 0; i < 4; ++i) {
            int ci = pc + 4 * i;
            float4 v = *(const float4*)(ar + pr * 256 + ((ci ^ (pr & 15)) << 4));
            int d = grow - ci * 4;
            if ((unsigned)d < 4u) ((float*)&v)[d] += 1.f;
            __stcs((float4*)(aog + ci * 4), v);
            __nv_bfloat162 h0 = __floats2bfloat162_rn(v.x, v.y);
            __nv_bfloat162 h1 = __floats2bfloat162_rn(v.z, v.w);
            *(uint2*)(af + swz(pr, ci >> 1) + (ci & 1) * 8) =
                make_uint2(*(uint32_t*)&h0, *(uint32_t*)&h1);
        }
    }
    __syncthreads();

    for (int it = 0; it < NIT; ++it) {
        int stage = it % 3;
        bool have_next = (it + 1 < NIT);
        if (it + 2 < NIT) mg3_load(in, smem, (it + 2) % 3, (it + 2) * 64, tid, m0);
        if (have_next) cp_wait<1>(); else cp_wait<0>();

        // issue raw-A loads for it+1 early (latency hides under mma below)
        float4 v[4];
        const char* arn = smem + ((it + 1) % 3) * MGS_STRIDE + MGS_AOFF;
        if (have_next) {
            #pragma unroll
            for (int i = 0; i < 4; ++i) {
                int ci = pc + 4 * i;
                v[i] = *(const float4*)(arn + pr * 256 + ((ci ^ (pr & 15)) << 4));
            }
        }

        // mma(it) from af(it&1) and B(stage)
        uint32_t Af = s2u(smem + MG_AF + (it & 1) * 8192);
        uint32_t Bs = s2u(smem + stage * MGS_STRIDE);
        #pragma unroll
        for (int kk = 0; kk < 4; ++kk) {
            uint32_t a[2][4];
            #pragma unroll
            for (int mi = 0; mi < 2; ++mi)
                ldsm4(a[mi], Af + swz(rowA[mi], kk * 2 + hiA));
            #pragma unroll
            for (int nb = 0; nb < 4; ++nb) {
                uint32_t b[4];
                ldsm4(b, Bs + swz(rowB[nb], kk * 2 + hiB));
                mma16816(acc[0][2 * nb],     a[0], b[0], b[1]);
                mma16816(acc[0][2 * nb + 1], a[0], b[2], b[3]);
                mma16816(acc[1][2 * nb],     a[1], b[0], b[1]);
                mma16816(acc[1][2 * nb + 1], a[1], b[2], b[3]);
            }
        }

        // finish processA(it+1): +I, streaming copy-out, bf16 STS into af(!(it&1))
        if (have_next) {
            int k1 = (it + 1) * 64;
            char* af = smem + MG_AF + ((it + 1) & 1) * 8192;
            #pragma unroll
            for (int i = 0; i < 4; ++i) {
                int ci = pc + 4 * i;
                int d = grow - (k1 + ci * 4);
                if ((unsigned)d < 4u) ((float*)&v[i])[d] += 1.f;
                __stcs((float4*)(aog + k1 + ci * 4), v[i]);
                __nv_bfloat162 h0 = __floats2bfloat162_rn(v[i].x, v[i].y);
                __nv_bfloat162 h1 = __floats2bfloat162_rn(v[i].z, v[i].w);
                *(uint2*)(af + swz(pr, ci >> 1) + (ci & 1) * 8) =
                    make_uint2(*(uint32_t*)&h0, *(uint32_t*)&h1);
            }
        }
        __syncthreads();
    }

    // epilogue: scale by dinv[row], store out[:, :256] (streaming)
    int qr = lane >> 2, qc = (lane & 3) * 2;
    #pragma unroll
    for (int mi = 0; mi < 2; ++mi) {
        int r0g = m0 + warp_m + mi * 16 + qr;
        float dv0 = g_dinv[r0g];
        float dv1 = g_dinv[r0g + 8];
        float* o0 = out + (size_t)r0g * OPITCH;
        float* o1 = o0 + (size_t)8 * OPITCH;
        #pragma unroll
        for (int n8 = 0; n8 < 8; ++n8) {
            int col = warp_n + n8 * 8 + qc;
            __stcs(&o0[col],     dv0 * acc[mi][n8][0]);
            __stcs(&o0[col + 1], dv0 * acc[mi][n8][1]);
            __stcs(&o1[col],     dv1 * acc[mi][n8][2]);
            __stcs(&o1[col + 1], dv1 * acc[mi][n8][3]);
        }
    }
}

// ---------------------------------------------------------------------------
extern "C" void kernel_launch(void* const* d_in, const int* in_sizes, int n_in,
                              void* d_out, int out_size) {
    const float* in = (const float*)d_in[0];
    const float* w  = (const float*)d_in[1];
    float* out = (float*)d_out;

    cudaFuncSetAttribute(support_mma, cudaFuncAttributeMaxDynamicSharedMemorySize, SP_TOTAL);
    cudaFuncSetAttribute(main_gemm4,  cudaFuncAttributeMaxDynamicSharedMemorySize, MG3_TOTAL);

    wt_kernel  <<<dim3(16, 8), 256>>>(w);
    colsum_part<<<dim3(8, 64), 256>>>(in);
    finalize_d <<<32, 256>>>();
    support_mma<<<128, 256, SP_TOTAL>>>(in);
    main_gemm4 <<<128, 256, MG3_TOTAL>>>(in, out);
}

// round 8
// speedup vs baseline: 1.0305x; 1.0305x over previous
#include <cuda_runtime.h>
#include <cuda_bf16.h>
#include <cstdint>

#define NSMP   8192
#define NA     512
#define DOUT   256
#define PITCH  8712   // input row length
#define ACOL0  512    // A starts at input col 512
#define OPITCH 8448   // output row length

// Scratch (static device globals — no runtime allocation)
__device__ float g_part[64 * NSMP];
__device__ float g_dinv[NSMP];
__device__ __align__(16) __nv_bfloat16 g_supT[(size_t)DOUT * NSMP]; // S_T[n][j]
__device__ __align__(16) __nv_bfloat16 g_WT[(size_t)DOUT * NA];     // W^T[n][k] bf16

// ---------------------------------------------------------------------------
// PTX helpers (base-target-safe)
// ---------------------------------------------------------------------------
__device__ __forceinline__ uint32_t s2u(const void* p) {
    return (uint32_t)__cvta_generic_to_shared(p);
}
__device__ __forceinline__ void cp_async16(uint32_t s, const void* g) {
    asm volatile("cp.async.cg.shared.global [%0], [%1], 16;" :: "r"(s), "l"(g) : "memory");
}
__device__ __forceinline__ void cp_commit() {
    asm volatile("cp.async.commit_group;" ::: "memory");
}
template <int N>
__device__ __forceinline__ void cp_wait() {
    asm volatile("cp.async.wait_group %0;" :: "n"(N) : "memory");
}
__device__ __forceinline__ void bar_sync(int id, int cnt) {
    asm volatile("bar.sync %0, %1;" :: "r"(id), "r"(cnt) : "memory");
}
__device__ __forceinline__ void bar_arrive(int id, int cnt) {
    asm volatile("bar.arrive %0, %1;" :: "r"(id), "r"(cnt) : "memory");
}
__device__ __forceinline__ void ldsm4(uint32_t* r, uint32_t addr) {
    asm volatile("ldmatrix.sync.aligned.m8n8.x4.shared.b16 {%0,%1,%2,%3}, [%4];"
                 : "=r"(r[0]), "=r"(r[1]), "=r"(r[2]), "=r"(r[3]) : "r"(addr));
}
__device__ __forceinline__ void mma16816(float* d, const uint32_t* a, uint32_t b0, uint32_t b1) {
    asm volatile(
        "mma.sync.aligned.m16n8k16.row.col.f32.bf16.bf16.f32 "
        "{%0,%1,%2,%3}, {%4,%5,%6,%7}, {%8,%9}, {%0,%1,%2,%3};"
        : "+f"(d[0]), "+f"(d[1]), "+f"(d[2]), "+f"(d[3])
        : "r"(a[0]), "r"(a[1]), "r"(a[2]), "r"(a[3]), "r"(b0), "r"(b1));
}
// SW128-swizzled smem offset for (row, 16B-chunk c) with 128B rows
__device__ __forceinline__ uint32_t swz(int row, int c) {
    return (uint32_t)(row * 128 + ((c ^ (row & 7)) << 4));
}

// ---------------------------------------------------------------------------
// Kernel: W^T bf16 (tiny, independent)
// ---------------------------------------------------------------------------
__global__ void wt_kernel(const float* __restrict__ w) {
    __shared__ float ts[32][33];
    int k0 = blockIdx.x * 32, n0 = blockIdx.y * 32;
    int t = threadIdx.x;
    int a = t >> 5, b = t & 31;
    #pragma unroll
    for (int i = 0; i < 4; ++i)
        ts[a + 8 * i][b] = w[(size_t)(k0 + a + 8 * i) * DOUT + n0 + b];
    __syncthreads();
    #pragma unroll
    for (int i = 0; i < 4; ++i)
        g_WT[(size_t)(n0 + a + 8 * i) * NA + k0 + b] = __float2bfloat16(ts[b][a + 8 * i]);
}

// ---------------------------------------------------------------------------
// Kernel: partial column sums of A (float4, deterministic)
// ---------------------------------------------------------------------------
__global__ void colsum_part(const float* __restrict__ in) {
    int col = (blockIdx.x * 256 + threadIdx.x) * 4;
    int r0  = blockIdx.y * 128;
    const float* p = in + (size_t)r0 * PITCH + ACOL0 + col;
    float4 s = make_float4(0.f, 0.f, 0.f, 0.f);
    #pragma unroll 8
    for (int r = 0; r < 128; ++r) {
        float4 v = *(const float4*)p;
        s.x += v.x; s.y += v.y; s.z += v.z; s.w += v.w;
        p += PITCH;
    }
    *(float4*)(g_part + blockIdx.y * NSMP + col) = s;
}

__global__ void finalize_d() {
    int col = blockIdx.x * 256 + threadIdx.x;
    float s = 1.0f;
    #pragma unroll
    for (int i = 0; i < 64; ++i) s += g_part[i * NSMP + col];
    g_dinv[col] = rsqrtf(s);
}

// ---------------------------------------------------------------------------
// support (mma.sync): S_T[n][j] = bf16( dinv[j] * (X @ W)[j,n] )  (unchanged)
// ---------------------------------------------------------------------------
#define SP_A0 0
#define SP_B0 8192
#define SP_A1 40960
#define SP_B1 49152
#define SP_TOTAL 81920
#define ST_PITCH 144

__device__ __forceinline__ void sp_load(const float* in, char* smem, int buf, int k0,
                                        int tid, int m0) {
    uint32_t bs = s2u(smem + (buf ? SP_B1 : SP_B0));
    const char* gB = (const char*)g_WT + (size_t)k0 * 2;
    #pragma unroll
    for (int c = 0; c < 8; ++c) {
        int chunk = tid + c * 256;
        int row = chunk >> 3;
        int seg = chunk & 7;
        cp_async16(bs + swz(row, seg), gB + (size_t)row * (NA * 2) + seg * 16);
    }
    cp_commit();
    char* As = smem + (buf ? SP_A1 : SP_A0);
    int f = tid & 15, r0 = tid >> 4;
    #pragma unroll
    for (int i = 0; i < 4; ++i) {
        int row = r0 + 16 * i;
        float4 v = *(const float4*)(in + (size_t)(m0 + row) * PITCH + k0 + f * 4);
        __nv_bfloat162 h0 = __floats2bfloat162_rn(v.x, v.y);
        __nv_bfloat162 h1 = __floats2bfloat162_rn(v.z, v.w);
        *(uint2*)(As + swz(row, f >> 1) + (f & 1) * 8) =
            make_uint2(*(uint32_t*)&h0, *(uint32_t*)&h1);
    }
}

__global__ void __launch_bounds__(256, 1) support_mma(const float* __restrict__ in) {
    extern __shared__ char smem[];
    int tid = threadIdx.x;
    int wid = tid >> 5, lane = tid & 31;
    int m0 = blockIdx.x * 64;
    int warp_m = (wid & 1) * 32;
    int warp_n = (wid >> 1) * 64;

    int rowA[2], rowB[4];
    #pragma unroll
    for (int mi = 0; mi < 2; ++mi) rowA[mi] = warp_m + mi * 16 + (lane & 15);
    int hiA = lane >> 4;
    #pragma unroll
    for (int nb = 0; nb < 4; ++nb)
        rowB[nb] = warp_n + nb * 16 + ((lane >> 4) << 3) + (lane & 7);
    int hiB = (lane >> 3) & 1;

    float acc[2][8][4] = {};

    sp_load(in, smem, 0, 0, tid, m0);
    for (int it = 0; it < NA / 64; ++it) {
        int buf = it & 1;
        if (it + 1 < NA / 64) { sp_load(in, smem, buf ^ 1, (it + 1) * 64, tid, m0); cp_wait<1>(); }
        else cp_wait<0>();
        __syncthreads();
        uint32_t As = s2u(smem + (buf ? SP_A1 : SP_A0));
        uint32_t Bs = s2u(smem + (buf ? SP_B1 : SP_B0));
        #pragma unroll
        for (int kk = 0; kk < 4; ++kk) {
            uint32_t a[2][4];
            #pragma unroll
            for (int mi = 0; mi < 2; ++mi)
                ldsm4(a[mi], As + swz(rowA[mi], kk * 2 + hiA));
            #pragma unroll
            for (int nb = 0; nb < 4; ++nb) {
                uint32_t b[4];
                ldsm4(b, Bs + swz(rowB[nb], kk * 2 + hiB));
                mma16816(acc[0][2 * nb],     a[0], b[0], b[1]);
                mma16816(acc[0][2 * nb + 1], a[0], b[2], b[3]);
                mma16816(acc[1][2 * nb],     a[1], b[0], b[1]);
                mma16816(acc[1][2 * nb + 1], a[1], b[2], b[3]);
            }
        }
        __syncthreads();
    }

    int qr = lane >> 2, qc = (lane & 3) * 2;
    #pragma unroll
    for (int mi = 0; mi < 2; ++mi) {
        int j0 = warp_m + mi * 16 + qr;
        float dv0 = g_dinv[m0 + j0];
        float dv1 = g_dinv[m0 + j0 + 8];
        #pragma unroll
        for (int n8 = 0; n8 < 8; ++n8) {
            int n = warp_n + n8 * 8 + qc;
            *(__nv_bfloat16*)(smem + n * ST_PITCH + j0 * 2)             = __float2bfloat16(dv0 * acc[mi][n8][0]);
            *(__nv_bfloat16*)(smem + (n + 1) * ST_PITCH + j0 * 2)       = __float2bfloat16(dv0 * acc[mi][n8][1]);
            *(__nv_bfloat16*)(smem + n * ST_PITCH + (j0 + 8) * 2)       = __float2bfloat16(dv1 * acc[mi][n8][2]);
            *(__nv_bfloat16*)(smem + (n + 1) * ST_PITCH + (j0 + 8) * 2) = __float2bfloat16(dv1 * acc[mi][n8][3]);
        }
    }
    __syncthreads();
    #pragma unroll
    for (int c = 0; c < 8; ++c) {
        int chunk = tid + c * 256;
        int n = chunk >> 3;
        int seg = chunk & 7;
        uint4 v = *(const uint4*)(smem + n * ST_PITCH + seg * 16);
        *(uint4*)((char*)g_supT + ((size_t)n * NSMP + m0) * 2 + seg * 16) = v;
    }
}

// ---------------------------------------------------------------------------
// main (warp-specialized): out[:, :256] = diag(dinv)*(A+I)@S ; out[:,256:]=A+I
// 384 threads: warps 0-7 = mma consumers, warps 8-11 = producers.
// Named barriers: READY0/1 (ids 1,2), FREE0/1 (ids 3,4), count 384.
// ---------------------------------------------------------------------------
#define MGS_STRIDE 49152   // per-stage: B(32KB) + Araw(16KB)
#define MGS_AOFF   32768
#define MG_AF      147456  // bf16 A, 2 x 8KB
#define MWS_TOTAL  163840
#define NIT        (NSMP / 64)
#define NTHREADS   384

__device__ __forceinline__ void ws_load(const float* in, char* smem, int stage, int k0,
                                        int lt, int m0) {
    // B tile: 2048 x 16B chunks, 16 per producer thread
    uint32_t bs = s2u(smem + stage * MGS_STRIDE);
    const char* gB = (const char*)g_supT + (size_t)k0 * 2;
    #pragma unroll
    for (int j = 0; j < 16; ++j) {
        int chunk = lt + 128 * j;
        int row = chunk >> 3;
        int seg = chunk & 7;
        cp_async16(bs + swz(row, seg), gB + (size_t)row * (NSMP * 2) + seg * 16);
    }
    // A raw fp32 tile 64x64 (1024 x 16B chunks), 8 per thread, coalesced mapping
    uint32_t ar = s2u(smem + stage * MGS_STRIDE + MGS_AOFF);
    const char* gA = (const char*)(in + (size_t)m0 * PITCH + ACOL0 + k0);
    #pragma unroll
    for (int i = 0; i < 8; ++i) {
        int idx = lt + 128 * i;
        int r = idx >> 4, ci = idx & 15;
        cp_async16(ar + r * 256 + ((ci ^ (r & 15)) << 4), gA + (size_t)r * PITCH * 4 + ci * 16);
    }
    cp_commit();
}

__global__ void __launch_bounds__(NTHREADS, 1) main_ws(const float* __restrict__ in,
                                                       float* __restrict__ out) {
    extern __shared__ char smem[];
    int tid = threadIdx.x;
    int wid = tid >> 5, lane = tid & 31;
    int m0 = blockIdx.x * 64;

    if (wid < 8) {
        // ------------------ CONSUMER: ldsm + mma only ------------------
        int warp_m = (wid & 1) * 32;
        int warp_n = (wid >> 1) * 64;
        int rowA[2], rowB[4];
        #pragma unroll
        for (int mi = 0; mi < 2; ++mi) rowA[mi] = warp_m + mi * 16 + (lane & 15);
        int hiA = lane >> 4;
        #pragma unroll
        for (int nb = 0; nb < 4; ++nb)
            rowB[nb] = warp_n + nb * 16 + ((lane >> 4) << 3) + (lane & 7);
        int hiB = (lane >> 3) & 1;

        float acc[2][8][4] = {};

        for (int c = 0; c < NIT; ++c) {
            bar_sync(1 + (c & 1), NTHREADS);                 // READY(c&1)
            uint32_t Af = s2u(smem + MG_AF + (c & 1) * 8192);
            uint32_t Bs = s2u(smem + (c % 3) * MGS_STRIDE);
            #pragma unroll
            for (int kk = 0; kk < 4; ++kk) {
                uint32_t a[2][4];
                #pragma unroll
                for (int mi = 0; mi < 2; ++mi)
                    ldsm4(a[mi], Af + swz(rowA[mi], kk * 2 + hiA));
                #pragma unroll
                for (int nb = 0; nb < 4; ++nb) {
                    uint32_t b[4];
                    ldsm4(b, Bs + swz(rowB[nb], kk * 2 + hiB));
                    mma16816(acc[0][2 * nb],     a[0], b[0], b[1]);
                    mma16816(acc[0][2 * nb + 1], a[0], b[2], b[3]);
                    mma16816(acc[1][2 * nb],     a[1], b[0], b[1]);
                    mma16816(acc[1][2 * nb + 1], a[1], b[2], b[3]);
                }
            }
            bar_arrive(3 + (c & 1), NTHREADS);               // FREE(c&1)
        }

        // epilogue: scale by dinv[row], streaming store out[:, :256]
        int qr = lane >> 2, qc = (lane & 3) * 2;
        #pragma unroll
        for (int mi = 0; mi < 2; ++mi) {
            int r0g = m0 + warp_m + mi * 16 + qr;
            float dv0 = g_dinv[r0g];
            float dv1 = g_dinv[r0g + 8];
            float* o0 = out + (size_t)r0g * OPITCH;
            float* o1 = o0 + (size_t)8 * OPITCH;
            #pragma unroll
            for (int n8 = 0; n8 < 8; ++n8) {
                int col = warp_n + n8 * 8 + qc;
                __stcs(&o0[col],     dv0 * acc[mi][n8][0]);
                __stcs(&o0[col + 1], dv0 * acc[mi][n8][1]);
                __stcs(&o1[col],     dv1 * acc[mi][n8][2]);
                __stcs(&o1[col + 1], dv1 * acc[mi][n8][3]);
            }
        }
    } else {
        // ------------------ PRODUCER: loads + processA ------------------
        int lt = tid - 256;   // 0..127

        ws_load(in, smem, 0, 0, lt, m0);
        ws_load(in, smem, 1, 64, lt, m0);

        for (int p = 0; p < NIT; ++p) {
            if (p >= 1) bar_sync(3 + ((p - 1) & 1), NTHREADS);   // FREE((p-1)&1)
            if (p < NIT - 1) cp_wait<1>(); else cp_wait<0>();

            // processA(p): +I, streaming A+I copy-out, bf16 swizzled STS
            {
                int k0 = p * 64;
                const char* ar = smem + (p % 3) * MGS_STRIDE + MGS_AOFF;
                char* af = smem + MG_AF + (p & 1) * 8192;
                #pragma unroll
                for (int i = 0; i < 8; ++i) {
                    int idx = lt + 128 * i;
                    int r = idx >> 4, ci = idx & 15;
                    float4 v = *(const float4*)(ar + r * 256 + ((ci ^ (r & 15)) << 4));
                    int grow = m0 + r;
                    int d = grow - (k0 + ci * 4);
                    if ((unsigned)d < 4u) ((float*)&v)[d] += 1.f;
                    __stcs((float4*)(out + (size_t)grow * OPITCH + DOUT + k0 + ci * 4), v);
                    __nv_bfloat162 h0 = __floats2bfloat162_rn(v.x, v.y);
                    __nv_bfloat162 h1 = __floats2bfloat162_rn(v.z, v.w);
                    *(uint2*)(af + swz(r, ci >> 1) + (ci & 1) * 8) =
                        make_uint2(*(uint32_t*)&h0, *(uint32_t*)&h1);
                }
            }
            bar_arrive(1 + (p & 1), NTHREADS);                   // READY(p&1)
            if (p + 2 < NIT) ws_load(in, smem, (p + 2) % 3, (p + 2) * 64, lt, m0);
        }
    }
}

// ---------------------------------------------------------------------------
extern "C" void kernel_launch(void* const* d_in, const int* in_sizes, int n_in,
                              void* d_out, int out_size) {
    const float* in = (const float*)d_in[0];
    const float* w  = (const float*)d_in[1];
    float* out = (float*)d_out;

    cudaFuncSetAttribute(support_mma, cudaFuncAttributeMaxDynamicSharedMemorySize, SP_TOTAL);
    cudaFuncSetAttribute(main_ws,     cudaFuncAttributeMaxDynamicSharedMemorySize, MWS_TOTAL);

    wt_kernel  <<<dim3(16, 8), 256>>>(w);
    colsum_part<<<dim3(8, 64), 256>>>(in);
    finalize_d <<<32, 256>>>();
    support_mma<<<128, 256, SP_TOTAL>>>(in);
    main_ws    <<<128, NTHREADS, MWS_TOTAL>>>(in, out);
}

// round 9
// speedup vs baseline: 1.1059x; 1.0732x over previous
#include <cuda_runtime.h>
#include <cuda_bf16.h>
#include <cstdint>

#define NSMP   8192
#define NA     512
#define DOUT   256
#define PITCH  8712   // input row length
#define ACOL0  512    // A starts at input col 512
#define OPITCH 8448   // output row length

// Scratch (static device globals — no runtime allocation)
__device__ float g_part[64 * NSMP];
__device__ float g_dinv[NSMP];
__device__ __align__(16) __nv_bfloat16 g_supT[(size_t)DOUT * NSMP]; // S_T[n][j]
__device__ __align__(16) __nv_bfloat16 g_WT[(size_t)DOUT * NA];     // W^T[n][k] bf16
__device__ __align__(16) __nv_bfloat16 g_Ab[(size_t)NSMP * NSMP];   // bf16(A+I)

// ---------------------------------------------------------------------------
// PTX helpers (base-target-safe)
// ---------------------------------------------------------------------------
__device__ __forceinline__ uint32_t s2u(const void* p) {
    return (uint32_t)__cvta_generic_to_shared(p);
}
__device__ __forceinline__ void cp_async16(uint32_t s, const void* g) {
    asm volatile("cp.async.cg.shared.global [%0], [%1], 16;" :: "r"(s), "l"(g) : "memory");
}
__device__ __forceinline__ void cp_commit() {
    asm volatile("cp.async.commit_group;" ::: "memory");
}
template <int N>
__device__ __forceinline__ void cp_wait() {
    asm volatile("cp.async.wait_group %0;" :: "n"(N) : "memory");
}
__device__ __forceinline__ void ldsm4(uint32_t* r, uint32_t addr) {
    asm volatile("ldmatrix.sync.aligned.m8n8.x4.shared.b16 {%0,%1,%2,%3}, [%4];"
                 : "=r"(r[0]), "=r"(r[1]), "=r"(r[2]), "=r"(r[3]) : "r"(addr));
}
__device__ __forceinline__ void mma16816(float* d, const uint32_t* a, uint32_t b0, uint32_t b1) {
    asm volatile(
        "mma.sync.aligned.m16n8k16.row.col.f32.bf16.bf16.f32 "
        "{%0,%1,%2,%3}, {%4,%5,%6,%7}, {%8,%9}, {%0,%1,%2,%3};"
        : "+f"(d[0]), "+f"(d[1]), "+f"(d[2]), "+f"(d[3])
        : "r"(a[0]), "r"(a[1]), "r"(a[2]), "r"(a[3]), "r"(b0), "r"(b1));
}
// SW128-swizzled smem offset for (row, 16B-chunk c) with 128B rows
__device__ __forceinline__ uint32_t swz(int row, int c) {
    return (uint32_t)(row * 128 + ((c ^ (row & 7)) << 4));
}

// ---------------------------------------------------------------------------
// Kernel: W^T bf16 (tiny, independent)
// ---------------------------------------------------------------------------
__global__ void wt_kernel(const float* __restrict__ w) {
    __shared__ float ts[32][33];
    int k0 = blockIdx.x * 32, n0 = blockIdx.y * 32;
    int t = threadIdx.x;
    int a = t >> 5, b = t & 31;
    #pragma unroll
    for (int i = 0; i < 4; ++i)
        ts[a + 8 * i][b] = w[(size_t)(k0 + a + 8 * i) * DOUT + n0 + b];
    __syncthreads();
    #pragma unroll
    for (int i = 0; i < 4; ++i)
        g_WT[(size_t)(n0 + a + 8 * i) * NA + k0 + b] = __float2bfloat16(ts[b][a + 8 * i]);
}

// ---------------------------------------------------------------------------
// Kernel: colsum partials + A+I copy-out (fp32) + bf16(A+I) production.
// One pass over A does all three. Deterministic partials as before.
// ---------------------------------------------------------------------------
__global__ void colsum_fused(const float* __restrict__ in, float* __restrict__ out) {
    int col = (blockIdx.x * 256 + threadIdx.x) * 4;
    int r0  = blockIdx.y * 128;
    const float* p = in + (size_t)r0 * PITCH + ACOL0 + col;
    float*       q = out + (size_t)r0 * OPITCH + DOUT + col;
    __nv_bfloat16* ab = g_Ab + (size_t)r0 * NSMP + col;
    float4 s = make_float4(0.f, 0.f, 0.f, 0.f);
    #pragma unroll 4
    for (int r = 0; r < 128; ++r) {
        float4 v = *(const float4*)p;
        s.x += v.x; s.y += v.y; s.z += v.z; s.w += v.w;   // raw A sums (pre-identity)
        int d = (r0 + r) - col;
        if ((unsigned)d < 4u) ((float*)&v)[d] += 1.f;     // +I
        __stcs((float4*)q, v);                            // fp32 A+I -> out[:,256:]
        __nv_bfloat162 h0 = __floats2bfloat162_rn(v.x, v.y);
        __nv_bfloat162 h1 = __floats2bfloat162_rn(v.z, v.w);
        *(uint2*)ab = make_uint2(*(uint32_t*)&h0, *(uint32_t*)&h1);
        p += PITCH; q += OPITCH; ab += NSMP;
    }
    *(float4*)(g_part + blockIdx.y * NSMP + col) = s;
}

__global__ void finalize_d() {
    int col = blockIdx.x * 256 + threadIdx.x;
    float s = 1.0f;
    #pragma unroll
    for (int i = 0; i < 64; ++i) s += g_part[i * NSMP + col];
    g_dinv[col] = rsqrtf(s);
}

// ---------------------------------------------------------------------------
// support (mma.sync): S_T[n][j] = bf16( dinv[j] * (X @ W)[j,n] )  (unchanged)
// ---------------------------------------------------------------------------
#define SP_A0 0
#define SP_B0 8192
#define SP_A1 40960
#define SP_B1 49152
#define SP_TOTAL 81920
#define ST_PITCH 144

__device__ __forceinline__ void sp_load(const float* in, char* smem, int buf, int k0,
                                        int tid, int m0) {
    uint32_t bs = s2u(smem + (buf ? SP_B1 : SP_B0));
    const char* gB = (const char*)g_WT + (size_t)k0 * 2;
    #pragma unroll
    for (int c = 0; c < 8; ++c) {
        int chunk = tid + c * 256;
        int row = chunk >> 3;
        int seg = chunk & 7;
        cp_async16(bs + swz(row, seg), gB + (size_t)row * (NA * 2) + seg * 16);
    }
    cp_commit();
    char* As = smem + (buf ? SP_A1 : SP_A0);
    int f = tid & 15, r0 = tid >> 4;
    #pragma unroll
    for (int i = 0; i < 4; ++i) {
        int row = r0 + 16 * i;
        float4 v = *(const float4*)(in + (size_t)(m0 + row) * PITCH + k0 + f * 4);
        __nv_bfloat162 h0 = __floats2bfloat162_rn(v.x, v.y);
        __nv_bfloat162 h1 = __floats2bfloat162_rn(v.z, v.w);
        *(uint2*)(As + swz(row, f >> 1) + (f & 1) * 8) =
            make_uint2(*(uint32_t*)&h0, *(uint32_t*)&h1);
    }
}

__global__ void __launch_bounds__(256, 1) support_mma(const float* __restrict__ in) {
    extern __shared__ char smem[];
    int tid = threadIdx.x;
    int wid = tid >> 5, lane = tid & 31;
    int m0 = blockIdx.x * 64;
    int warp_m = (wid & 1) * 32;
    int warp_n = (wid >> 1) * 64;

    int rowA[2], rowB[4];
    #pragma unroll
    for (int mi = 0; mi < 2; ++mi) rowA[mi] = warp_m + mi * 16 + (lane & 15);
    int hiA = lane >> 4;
    #pragma unroll
    for (int nb = 0; nb < 4; ++nb)
        rowB[nb] = warp_n + nb * 16 + ((lane >> 4) << 3) + (lane & 7);
    int hiB = (lane >> 3) & 1;

    float acc[2][8][4] = {};

    sp_load(in, smem, 0, 0, tid, m0);
    for (int it = 0; it < NA / 64; ++it) {
        int buf = it & 1;
        if (it + 1 < NA / 64) { sp_load(in, smem, buf ^ 1, (it + 1) * 64, tid, m0); cp_wait<1>(); }
        else cp_wait<0>();
        __syncthreads();
        uint32_t As = s2u(smem + (buf ? SP_A1 : SP_A0));
        uint32_t Bs = s2u(smem + (buf ? SP_B1 : SP_B0));
        #pragma unroll
        for (int kk = 0; kk < 4; ++kk) {
            uint32_t a[2][4];
            #pragma unroll
            for (int mi = 0; mi < 2; ++mi)
                ldsm4(a[mi], As + swz(rowA[mi], kk * 2 + hiA));
            #pragma unroll
            for (int nb = 0; nb < 4; ++nb) {
                uint32_t b[4];
                ldsm4(b, Bs + swz(rowB[nb], kk * 2 + hiB));
                mma16816(acc[0][2 * nb],     a[0], b[0], b[1]);
                mma16816(acc[0][2 * nb + 1], a[0], b[2], b[3]);
                mma16816(acc[1][2 * nb],     a[1], b[0], b[1]);
                mma16816(acc[1][2 * nb + 1], a[1], b[2], b[3]);
            }
        }
        __syncthreads();
    }

    int qr = lane >> 2, qc = (lane & 3) * 2;
    #pragma unroll
    for (int mi = 0; mi < 2; ++mi) {
        int j0 = warp_m + mi * 16 + qr;
        float dv0 = g_dinv[m0 + j0];
        float dv1 = g_dinv[m0 + j0 + 8];
        #pragma unroll
        for (int n8 = 0; n8 < 8; ++n8) {
            int n = warp_n + n8 * 8 + qc;
            *(__nv_bfloat16*)(smem + n * ST_PITCH + j0 * 2)             = __float2bfloat16(dv0 * acc[mi][n8][0]);
            *(__nv_bfloat16*)(smem + (n + 1) * ST_PITCH + j0 * 2)       = __float2bfloat16(dv0 * acc[mi][n8][1]);
            *(__nv_bfloat16*)(smem + n * ST_PITCH + (j0 + 8) * 2)       = __float2bfloat16(dv1 * acc[mi][n8][2]);
            *(__nv_bfloat16*)(smem + (n + 1) * ST_PITCH + (j0 + 8) * 2) = __float2bfloat16(dv1 * acc[mi][n8][3]);
        }
    }
    __syncthreads();
    #pragma unroll
    for (int c = 0; c < 8; ++c) {
        int chunk = tid + c * 256;
        int n = chunk >> 3;
        int seg = chunk & 7;
        uint4 v = *(const uint4*)(smem + n * ST_PITCH + seg * 16);
        *(uint4*)((char*)g_supT + ((size_t)n * NSMP + m0) * 2 + seg * 16) = v;
    }
}

// ---------------------------------------------------------------------------
// main (pure bf16 GEMM): out[:, :256] = diag(dinv) * bf16(A+I) @ S
// CTA 64x256, grid 128, 3-stage cp.async ring, ONE sync per iter, no stores
// in the mainloop. A comes pre-converted from g_Ab.
// ---------------------------------------------------------------------------
#define MG5_STRIDE 40960   // per-stage: B(32KB) + Abf16(8KB)
#define MG5_AOFF   32768
#define MG5_TOTAL  122880
#define NIT        (NSMP / 64)

__device__ __forceinline__ void mg5_load(char* smem, int stage, int k0, int tid, int m0) {
    // B tile: 256 x 64 bf16 (2048 chunks, 8 per thread)
    uint32_t bs = s2u(smem + stage * MG5_STRIDE);
    const char* gB = (const char*)g_supT + (size_t)k0 * 2;
    #pragma unroll
    for (int c = 0; c < 8; ++c) {
        int chunk = tid + c * 256;
        int row = chunk >> 3;
        int seg = chunk & 7;
        cp_async16(bs + swz(row, seg), gB + (size_t)row * (NSMP * 2) + seg * 16);
    }
    // A tile: 64 x 64 bf16 (512 chunks, 2 per thread)
    uint32_t as_ = s2u(smem + stage * MG5_STRIDE + MG5_AOFF);
    const char* gA = (const char*)g_Ab + (size_t)m0 * (NSMP * 2) + (size_t)k0 * 2;
    #pragma unroll
    for (int c = 0; c < 2; ++c) {
        int chunk = tid + c * 256;
        int row = chunk >> 3;
        int seg = chunk & 7;
        cp_async16(as_ + swz(row, seg), gA + (size_t)row * (NSMP * 2) + seg * 16);
    }
    cp_commit();
}

__global__ void __launch_bounds__(256, 1) main_gemm5(float* __restrict__ out) {
    extern __shared__ char smem[];
    int tid = threadIdx.x;
    int wid = tid >> 5, lane = tid & 31;
    int m0 = blockIdx.x * 64;
    int warp_m = (wid & 1) * 32;
    int warp_n = (wid >> 1) * 64;

    int rowA[2], rowB[4];
    #pragma unroll
    for (int mi = 0; mi < 2; ++mi) rowA[mi] = warp_m + mi * 16 + (lane & 15);
    int hiA = lane >> 4;
    #pragma unroll
    for (int nb = 0; nb < 4; ++nb)
        rowB[nb] = warp_n + nb * 16 + ((lane >> 4) << 3) + (lane & 7);
    int hiB = (lane >> 3) & 1;

    float acc[2][8][4] = {};

    mg5_load(smem, 0, 0, tid, m0);
    mg5_load(smem, 1, 64, tid, m0);

    for (int it = 0; it < NIT; ++it) {
        int stage = it % 3;
        if (it + 1 < NIT) cp_wait<1>(); else cp_wait<0>();
        __syncthreads();
        if (it + 2 < NIT) mg5_load(smem, (it + 2) % 3, (it + 2) * 64, tid, m0);

        uint32_t Af = s2u(smem + stage * MG5_STRIDE + MG5_AOFF);
        uint32_t Bs = s2u(smem + stage * MG5_STRIDE);
        #pragma unroll
        for (int kk = 0; kk < 4; ++kk) {
            uint32_t a[2][4];
            #pragma unroll
            for (int mi = 0; mi < 2; ++mi)
                ldsm4(a[mi], Af + swz(rowA[mi], kk * 2 + hiA));
            #pragma unroll
            for (int nb = 0; nb < 4; ++nb) {
                uint32_t b[4];
                ldsm4(b, Bs + swz(rowB[nb], kk * 2 + hiB));
                mma16816(acc[0][2 * nb],     a[0], b[0], b[1]);
                mma16816(acc[0][2 * nb + 1], a[0], b[2], b[3]);
                mma16816(acc[1][2 * nb],     a[1], b[0], b[1]);
                mma16816(acc[1][2 * nb + 1], a[1], b[2], b[3]);
            }
        }
    }

    // epilogue: scale by dinv[row], store out[:, :256]
    int qr = lane >> 2, qc = (lane & 3) * 2;
    #pragma unroll
    for (int mi = 0; mi < 2; ++mi) {
        int r0g = m0 + warp_m + mi * 16 + qr;
        float dv0 = g_dinv[r0g];
        float dv1 = g_dinv[r0g + 8];
        float* o0 = out + (size_t)r0g * OPITCH;
        float* o1 = o0 + (size_t)8 * OPITCH;
        #pragma unroll
        for (int n8 = 0; n8 < 8; ++n8) {
            int col = warp_n + n8 * 8 + qc;
            o0[col]     = dv0 * acc[mi][n8][0];
            o0[col + 1] = dv0 * acc[mi][n8][1];
            o1[col]     = dv1 * acc[mi][n8][2];
            o1[col + 1] = dv1 * acc[mi][n8][3];
        }
    }
}

// ---------------------------------------------------------------------------
extern "C" void kernel_launch(void* const* d_in, const int* in_sizes, int n_in,
                              void* d_out, int out_size) {
    const float* in = (const float*)d_in[0];
    const float* w  = (const float*)d_in[1];
    float* out = (float*)d_out;

    cudaFuncSetAttribute(support_mma, cudaFuncAttributeMaxDynamicSharedMemorySize, SP_TOTAL);
    cudaFuncSetAttribute(main_gemm5,  cudaFuncAttributeMaxDynamicSharedMemorySize, MG5_TOTAL);

    wt_kernel   <<<dim3(16, 8), 256>>>(w);
    colsum_fused<<<dim3(8, 64), 256>>>(in, out);
    finalize_d  <<<32, 256>>>();
    support_mma <<<128, 256, SP_TOTAL>>>(in);
    main_gemm5  <<<128, 256, MG5_TOTAL>>>(out);
}

// round 10
// speedup vs baseline: 1.1157x; 1.0088x over previous
#include <cuda_runtime.h>
#include <cuda_bf16.h>
#include <cstdint>

#define NSMP   8192
#define NA     512
#define DOUT   256
#define PITCH  8712   // input row length
#define ACOL0  512    // A starts at input col 512
#define OPITCH 8448   // output row length

// Scratch (static device globals — no runtime allocation)
__device__ float g_part[64 * NSMP];
__device__ float g_dinv[NSMP];
__device__ __align__(16) __nv_bfloat16 g_supT[(size_t)DOUT * NSMP]; // S_T[n][j]
__device__ __align__(16) __nv_bfloat16 g_WT[(size_t)DOUT * NA];     // W^T[n][k] bf16
__device__ __align__(16) __nv_bfloat16 g_Ab[(size_t)NSMP * NSMP];   // bf16(A+I)

// ---------------------------------------------------------------------------
// PTX helpers (base-target-safe)
// ---------------------------------------------------------------------------
__device__ __forceinline__ uint32_t s2u(const void* p) {
    return (uint32_t)__cvta_generic_to_shared(p);
}
__device__ __forceinline__ void cp_async16(uint32_t s, const void* g) {
    asm volatile("cp.async.cg.shared.global [%0], [%1], 16;" :: "r"(s), "l"(g) : "memory");
}
__device__ __forceinline__ void cp_commit() {
    asm volatile("cp.async.commit_group;" ::: "memory");
}
template <int N>
__device__ __forceinline__ void cp_wait() {
    asm volatile("cp.async.wait_group %0;" :: "n"(N) : "memory");
}
__device__ __forceinline__ void ldsm4(uint32_t* r, uint32_t addr) {
    asm volatile("ldmatrix.sync.aligned.m8n8.x4.shared.b16 {%0,%1,%2,%3}, [%4];"
                 : "=r"(r[0]), "=r"(r[1]), "=r"(r[2]), "=r"(r[3]) : "r"(addr));
}
__device__ __forceinline__ void mma16816(float* d, const uint32_t* a, uint32_t b0, uint32_t b1) {
    asm volatile(
        "mma.sync.aligned.m16n8k16.row.col.f32.bf16.bf16.f32 "
        "{%0,%1,%2,%3}, {%4,%5,%6,%7}, {%8,%9}, {%0,%1,%2,%3};"
        : "+f"(d[0]), "+f"(d[1]), "+f"(d[2]), "+f"(d[3])
        : "r"(a[0]), "r"(a[1]), "r"(a[2]), "r"(a[3]), "r"(b0), "r"(b1));
}
// SW128-swizzled smem offset for (row, 16B-chunk c) with 128B rows
__device__ __forceinline__ uint32_t swz(int row, int c) {
    return (uint32_t)(row * 128 + ((c ^ (row & 7)) << 4));
}

// ---------------------------------------------------------------------------
// Kernel: W^T bf16 (tiny, independent)
// ---------------------------------------------------------------------------
__global__ void wt_kernel(const float* __restrict__ w) {
    __shared__ float ts[32][33];
    int k0 = blockIdx.x * 32, n0 = blockIdx.y * 32;
    int t = threadIdx.x;
    int a = t >> 5, b = t & 31;
    #pragma unroll
    for (int i = 0; i < 4; ++i)
        ts[a + 8 * i][b] = w[(size_t)(k0 + a + 8 * i) * DOUT + n0 + b];
    __syncthreads();
    #pragma unroll
    for (int i = 0; i < 4; ++i)
        g_WT[(size_t)(n0 + a + 8 * i) * NA + k0 + b] = __float2bfloat16(ts[b][a + 8 * i]);
}

// ---------------------------------------------------------------------------
// Kernel: colsum partials + A+I copy-out (fp32) + bf16(A+I) production.
// ---------------------------------------------------------------------------
__global__ void colsum_fused(const float* __restrict__ in, float* __restrict__ out) {
    int col = (blockIdx.x * 256 + threadIdx.x) * 4;
    int r0  = blockIdx.y * 128;
    const float* p = in + (size_t)r0 * PITCH + ACOL0 + col;
    float*       q = out + (size_t)r0 * OPITCH + DOUT + col;
    __nv_bfloat16* ab = g_Ab + (size_t)r0 * NSMP + col;
    float4 s = make_float4(0.f, 0.f, 0.f, 0.f);
    #pragma unroll 4
    for (int r = 0; r < 128; ++r) {
        float4 v = *(const float4*)p;
        s.x += v.x; s.y += v.y; s.z += v.z; s.w += v.w;   // raw A sums (pre-identity)
        int d = (r0 + r) - col;
        if ((unsigned)d < 4u) ((float*)&v)[d] += 1.f;     // +I
        __stcs((float4*)q, v);                            // fp32 A+I -> out[:,256:]
        __nv_bfloat162 h0 = __floats2bfloat162_rn(v.x, v.y);
        __nv_bfloat162 h1 = __floats2bfloat162_rn(v.z, v.w);
        *(uint2*)ab = make_uint2(*(uint32_t*)&h0, *(uint32_t*)&h1);
        p += PITCH; q += OPITCH; ab += NSMP;
    }
    *(float4*)(g_part + blockIdx.y * NSMP + col) = s;
}

__global__ void finalize_d() {
    int col = blockIdx.x * 256 + threadIdx.x;
    float s = 1.0f;
    #pragma unroll
    for (int i = 0; i < 64; ++i) s += g_part[i * NSMP + col];
    g_dinv[col] = rsqrtf(s);
}

// ---------------------------------------------------------------------------
// support (mma.sync): S_T[n][j] = bf16( dinv[j] * (X @ W)[j,n] )  (unchanged)
// ---------------------------------------------------------------------------
#define SP_A0 0
#define SP_B0 8192
#define SP_A1 40960
#define SP_B1 49152
#define SP_TOTAL 81920
#define ST_PITCH 144

__device__ __forceinline__ void sp_load(const float* in, char* smem, int buf, int k0,
                                        int tid, int m0) {
    uint32_t bs = s2u(smem + (buf ? SP_B1 : SP_B0));
    const char* gB = (const char*)g_WT + (size_t)k0 * 2;
    #pragma unroll
    for (int c = 0; c < 8; ++c) {
        int chunk = tid + c * 256;
        int row = chunk >> 3;
        int seg = chunk & 7;
        cp_async16(bs + swz(row, seg), gB + (size_t)row * (NA * 2) + seg * 16);
    }
    cp_commit();
    char* As = smem + (buf ? SP_A1 : SP_A0);
    int f = tid & 15, r0 = tid >> 4;
    #pragma unroll
    for (int i = 0; i < 4; ++i) {
        int row = r0 + 16 * i;
        float4 v = *(const float4*)(in + (size_t)(m0 + row) * PITCH + k0 + f * 4);
        __nv_bfloat162 h0 = __floats2bfloat162_rn(v.x, v.y);
        __nv_bfloat162 h1 = __floats2bfloat162_rn(v.z, v.w);
        *(uint2*)(As + swz(row, f >> 1) + (f & 1) * 8) =
            make_uint2(*(uint32_t*)&h0, *(uint32_t*)&h1);
    }
}

__global__ void __launch_bounds__(256, 1) support_mma(const float* __restrict__ in) {
    extern __shared__ char smem[];
    int tid = threadIdx.x;
    int wid = tid >> 5, lane = tid & 31;
    int m0 = blockIdx.x * 64;
    int warp_m = (wid & 1) * 32;
    int warp_n = (wid >> 1) * 64;

    int rowA[2], rowB[4];
    #pragma unroll
    for (int mi = 0; mi < 2; ++mi) rowA[mi] = warp_m + mi * 16 + (lane & 15);
    int hiA = lane >> 4;
    #pragma unroll
    for (int nb = 0; nb < 4; ++nb)
        rowB[nb] = warp_n + nb * 16 + ((lane >> 4) << 3) + (lane & 7);
    int hiB = (lane >> 3) & 1;

    float acc[2][8][4] = {};

    sp_load(in, smem, 0, 0, tid, m0);
    for (int it = 0; it < NA / 64; ++it) {
        int buf = it & 1;
        if (it + 1 < NA / 64) { sp_load(in, smem, buf ^ 1, (it + 1) * 64, tid, m0); cp_wait<1>(); }
        else cp_wait<0>();
        __syncthreads();
        uint32_t As = s2u(smem + (buf ? SP_A1 : SP_A0));
        uint32_t Bs = s2u(smem + (buf ? SP_B1 : SP_B0));
        #pragma unroll
        for (int kk = 0; kk < 4; ++kk) {
            uint32_t a[2][4];
            #pragma unroll
            for (int mi = 0; mi < 2; ++mi)
                ldsm4(a[mi], As + swz(rowA[mi], kk * 2 + hiA));
            #pragma unroll
            for (int nb = 0; nb < 4; ++nb) {
                uint32_t b[4];
                ldsm4(b, Bs + swz(rowB[nb], kk * 2 + hiB));
                mma16816(acc[0][2 * nb],     a[0], b[0], b[1]);
                mma16816(acc[0][2 * nb + 1], a[0], b[2], b[3]);
                mma16816(acc[1][2 * nb],     a[1], b[0], b[1]);
                mma16816(acc[1][2 * nb + 1], a[1], b[2], b[3]);
            }
        }
        __syncthreads();
    }

    int qr = lane >> 2, qc = (lane & 3) * 2;
    #pragma unroll
    for (int mi = 0; mi < 2; ++mi) {
        int j0 = warp_m + mi * 16 + qr;
        float dv0 = g_dinv[m0 + j0];
        float dv1 = g_dinv[m0 + j0 + 8];
        #pragma unroll
        for (int n8 = 0; n8 < 8; ++n8) {
            int n = warp_n + n8 * 8 + qc;
            *(__nv_bfloat16*)(smem + n * ST_PITCH + j0 * 2)             = __float2bfloat16(dv0 * acc[mi][n8][0]);
            *(__nv_bfloat16*)(smem + (n + 1) * ST_PITCH + j0 * 2)       = __float2bfloat16(dv0 * acc[mi][n8][1]);
            *(__nv_bfloat16*)(smem + n * ST_PITCH + (j0 + 8) * 2)       = __float2bfloat16(dv1 * acc[mi][n8][2]);
            *(__nv_bfloat16*)(smem + (n + 1) * ST_PITCH + (j0 + 8) * 2) = __float2bfloat16(dv1 * acc[mi][n8][3]);
        }
    }
    __syncthreads();
    #pragma unroll
    for (int c = 0; c < 8; ++c) {
        int chunk = tid + c * 256;
        int n = chunk >> 3;
        int seg = chunk & 7;
        uint4 v = *(const uint4*)(smem + n * ST_PITCH + seg * 16);
        *(uint4*)((char*)g_supT + ((size_t)n * NSMP + m0) * 2 + seg * 16) = v;
    }
}

// ---------------------------------------------------------------------------
// main (pure bf16 GEMM): out[:, :256] = diag(dinv) * bf16(A+I) @ S
// CTA 64x128, grid (128, 2), 2 CTAs/SM, 4-stage cp.async ring, warp 32x32.
// ---------------------------------------------------------------------------
#define MG6_STRIDE 24576   // per-stage: B(16KB) + A(8KB)
#define MG6_AOFF   16384
#define MG6_TOTAL  98304   // 4 stages
#define NIT        (NSMP / 64)

__device__ __forceinline__ void mg6_load(char* smem, int stage, int k0, int tid,
                                         int m0, int n0) {
    // B tile: 128 x 64 bf16 (1024 chunks, 4 per thread)
    uint32_t bs = s2u(smem + stage * MG6_STRIDE);
    const char* gB = (const char*)g_supT + (size_t)(n0) * (NSMP * 2) + (size_t)k0 * 2;
    #pragma unroll
    for (int c = 0; c < 4; ++c) {
        int chunk = tid + c * 256;
        int row = chunk >> 3;
        int seg = chunk & 7;
        cp_async16(bs + swz(row, seg), gB + (size_t)row * (NSMP * 2) + seg * 16);
    }
    // A tile: 64 x 64 bf16 (512 chunks, 2 per thread)
    uint32_t as_ = s2u(smem + stage * MG6_STRIDE + MG6_AOFF);
    const char* gA = (const char*)g_Ab + (size_t)m0 * (NSMP * 2) + (size_t)k0 * 2;
    #pragma unroll
    for (int c = 0; c < 2; ++c) {
        int chunk = tid + c * 256;
        int row = chunk >> 3;
        int seg = chunk & 7;
        cp_async16(as_ + swz(row, seg), gA + (size_t)row * (NSMP * 2) + seg * 16);
    }
    cp_commit();
}

__global__ void __launch_bounds__(256, 2) main_gemm6(float* __restrict__ out) {
    extern __shared__ char smem[];
    int tid = threadIdx.x;
    int wid = tid >> 5, lane = tid & 31;
    int m0 = blockIdx.x * 64;
    int n0 = blockIdx.y * 128;
    int warp_m = (wid & 1) * 32;
    int warp_n = (wid >> 1) * 32;

    int rowA[2], rowB[2];
    #pragma unroll
    for (int mi = 0; mi < 2; ++mi) rowA[mi] = warp_m + mi * 16 + (lane & 15);
    int hiA = lane >> 4;
    #pragma unroll
    for (int nb = 0; nb < 2; ++nb)
        rowB[nb] = warp_n + nb * 16 + ((lane >> 4) << 3) + (lane & 7);
    int hiB = (lane >> 3) & 1;

    float acc[2][4][4] = {};

    mg6_load(smem, 0, 0, tid, m0, n0);
    mg6_load(smem, 1, 64, tid, m0, n0);
    mg6_load(smem, 2, 128, tid, m0, n0);

    for (int it = 0; it < NIT; ++it) {
        int stage = it & 3;
        if (it + 2 < NIT) cp_wait<2>();
        else if (it + 1 < NIT) cp_wait<1>();
        else cp_wait<0>();
        __syncthreads();
        if (it + 3 < NIT) mg6_load(smem, (it + 3) & 3, (it + 3) * 64, tid, m0, n0);

        uint32_t Af = s2u(smem + stage * MG6_STRIDE + MG6_AOFF);
        uint32_t Bs = s2u(smem + stage * MG6_STRIDE);
        #pragma unroll
        for (int kk = 0; kk < 4; ++kk) {
            uint32_t a[2][4];
            #pragma unroll
            for (int mi = 0; mi < 2; ++mi)
                ldsm4(a[mi], Af + swz(rowA[mi], kk * 2 + hiA));
            #pragma unroll
            for (int nb = 0; nb < 2; ++nb) {
                uint32_t b[4];
                ldsm4(b, Bs + swz(rowB[nb], kk * 2 + hiB));
                mma16816(acc[0][2 * nb],     a[0], b[0], b[1]);
                mma16816(acc[0][2 * nb + 1], a[0], b[2], b[3]);
                mma16816(acc[1][2 * nb],     a[1], b[0], b[1]);
                mma16816(acc[1][2 * nb + 1], a[1], b[2], b[3]);
            }
        }
    }

    // epilogue: scale by dinv[row], store out[:, n0 + warp_n ...]
    int qr = lane >> 2, qc = (lane & 3) * 2;
    #pragma unroll
    for (int mi = 0; mi < 2; ++mi) {
        int r0g = m0 + warp_m + mi * 16 + qr;
        float dv0 = g_dinv[r0g];
        float dv1 = g_dinv[r0g + 8];
        float* o0 = out + (size_t)r0g * OPITCH + n0;
        float* o1 = o0 + (size_t)8 * OPITCH;
        #pragma unroll
        for (int n8 = 0; n8 < 4; ++n8) {
            int col = warp_n + n8 * 8 + qc;
            o0[col]     = dv0 * acc[mi][n8][0];
            o0[col + 1] = dv0 * acc[mi][n8][1];
            o1[col]     = dv1 * acc[mi][n8][2];
            o1[col + 1] = dv1 * acc[mi][n8][3];
        }
    }
}

// ---------------------------------------------------------------------------
extern "C" void kernel_launch(void* const* d_in, const int* in_sizes, int n_in,
                              void* d_out, int out_size) {
    const float* in = (const float*)d_in[0];
    const float* w  = (const float*)d_in[1];
    float* out = (float*)d_out;

    cudaFuncSetAttribute(support_mma, cudaFuncAttributeMaxDynamicSharedMemorySize, SP_TOTAL);
    cudaFuncSetAttribute(main_gemm6,  cudaFuncAttributeMaxDynamicSharedMemorySize, MG6_TOTAL);

    wt_kernel   <<<dim3(16, 8), 256>>>(w);
    colsum_fused<<<dim3(8, 64), 256>>>(in, out);
    finalize_d  <<<32, 256>>>();
    support_mma <<<128, 256, SP_TOTAL>>>(in);
    main_gemm6  <<<dim3(128, 2), 256, MG6_TOTAL>>>(out);
}

// round 11
// speedup vs baseline: 1.2328x; 1.1049x over previous
#include <cuda_runtime.h>
#include <cuda_bf16.h>
#include <cstdint>

#define NSMP   8192
#define NA     512
#define DOUT   256
#define PITCH  8712   // input row length
#define ACOL0  512    // A starts at input col 512
#define OPITCH 8448   // output row length

// Scratch (static device globals — no runtime allocation)
__device__ float g_part[64 * NSMP];
__device__ float g_dinv[NSMP];
__device__ __align__(16) __nv_bfloat16 g_supT[(size_t)DOUT * NSMP]; // S_T[n][j]
__device__ __align__(16) __nv_bfloat16 g_WT[(size_t)DOUT * NA];     // W^T[n][k] bf16
__device__ __align__(16) __nv_bfloat16 g_Ab[(size_t)NSMP * NSMP];   // bf16(A+I)

// ---------------------------------------------------------------------------
// PTX helpers (base-target-safe)
// ---------------------------------------------------------------------------
__device__ __forceinline__ uint32_t s2u(const void* p) {
    return (uint32_t)__cvta_generic_to_shared(p);
}
__device__ __forceinline__ void cp_async16(uint32_t s, const void* g) {
    asm volatile("cp.async.cg.shared.global [%0], [%1], 16;" :: "r"(s), "l"(g) : "memory");
}
__device__ __forceinline__ void cp_commit() {
    asm volatile("cp.async.commit_group;" ::: "memory");
}
template <int N>
__device__ __forceinline__ void cp_wait() {
    asm volatile("cp.async.wait_group %0;" :: "n"(N) : "memory");
}
__device__ __forceinline__ void ldsm4(uint32_t* r, uint32_t addr) {
    asm volatile("ldmatrix.sync.aligned.m8n8.x4.shared.b16 {%0,%1,%2,%3}, [%4];"
                 : "=r"(r[0]), "=r"(r[1]), "=r"(r[2]), "=r"(r[3]) : "r"(addr));
}
__device__ __forceinline__ void mma16816(float* d, const uint32_t* a, uint32_t b0, uint32_t b1) {
    asm volatile(
        "mma.sync.aligned.m16n8k16.row.col.f32.bf16.bf16.f32 "
        "{%0,%1,%2,%3}, {%4,%5,%6,%7}, {%8,%9}, {%0,%1,%2,%3};"
        : "+f"(d[0]), "+f"(d[1]), "+f"(d[2]), "+f"(d[3])
        : "r"(a[0]), "r"(a[1]), "r"(a[2]), "r"(a[3]), "r"(b0), "r"(b1));
}
// SW128-swizzled smem offset for (row, 16B-chunk c) with 128B rows
__device__ __forceinline__ uint32_t swz(int row, int c) {
    return (uint32_t)(row * 128 + ((c ^ (row & 7)) << 4));
}

// ---------------------------------------------------------------------------
// Kernel: W^T bf16 (tiny, independent)
// ---------------------------------------------------------------------------
__global__ void wt_kernel(const float* __restrict__ w) {
    __shared__ float ts[32][33];
    int k0 = blockIdx.x * 32, n0 = blockIdx.y * 32;
    int t = threadIdx.x;
    int a = t >> 5, b = t & 31;
    #pragma unroll
    for (int i = 0; i < 4; ++i)
        ts[a + 8 * i][b] = w[(size_t)(k0 + a + 8 * i) * DOUT + n0 + b];
    __syncthreads();
    #pragma unroll
    for (int i = 0; i < 4; ++i)
        g_WT[(size_t)(n0 + a + 8 * i) * NA + k0 + b] = __float2bfloat16(ts[b][a + 8 * i]);
}

// ---------------------------------------------------------------------------
// Kernel: colsum partials + A+I copy-out (fp32) + bf16(A+I) production.
// ---------------------------------------------------------------------------
__global__ void colsum_fused(const float* __restrict__ in, float* __restrict__ out) {
    int col = (blockIdx.x * 256 + threadIdx.x) * 4;
    int r0  = blockIdx.y * 128;
    const float* p = in + (size_t)r0 * PITCH + ACOL0 + col;
    float*       q = out + (size_t)r0 * OPITCH + DOUT + col;
    __nv_bfloat16* ab = g_Ab + (size_t)r0 * NSMP + col;
    float4 s = make_float4(0.f, 0.f, 0.f, 0.f);
    #pragma unroll 4
    for (int r = 0; r < 128; ++r) {
        float4 v = *(const float4*)p;
        s.x += v.x; s.y += v.y; s.z += v.z; s.w += v.w;   // raw A sums (pre-identity)
        int d = (r0 + r) - col;
        if ((unsigned)d < 4u) ((float*)&v)[d] += 1.f;     // +I
        __stcs((float4*)q, v);                            // fp32 A+I -> out[:,256:]
        __nv_bfloat162 h0 = __floats2bfloat162_rn(v.x, v.y);
        __nv_bfloat162 h1 = __floats2bfloat162_rn(v.z, v.w);
        __stcs((uint2*)ab, make_uint2(*(uint32_t*)&h0, *(uint32_t*)&h1));
        p += PITCH; q += OPITCH; ab += NSMP;
    }
    *(float4*)(g_part + blockIdx.y * NSMP + col) = s;
}

__global__ void finalize_d() {
    int col = blockIdx.x * 256 + threadIdx.x;
    float s = 1.0f;
    #pragma unroll
    for (int i = 0; i < 64; ++i) s += g_part[i * NSMP + col];
    g_dinv[col] = rsqrtf(s);
}

// ---------------------------------------------------------------------------
// support (mma.sync): S_T[n][j] = bf16( dinv[j] * (X @ W)[j,n] )  (unchanged)
// ---------------------------------------------------------------------------
#define SP_A0 0
#define SP_B0 8192
#define SP_A1 40960
#define SP_B1 49152
#define SP_TOTAL 81920
#define ST_PITCH 144

__device__ __forceinline__ void sp_load(const float* in, char* smem, int buf, int k0,
                                        int tid, int m0) {
    uint32_t bs = s2u(smem + (buf ? SP_B1 : SP_B0));
    const char* gB = (const char*)g_WT + (size_t)k0 * 2;
    #pragma unroll
    for (int c = 0; c < 8; ++c) {
        int chunk = tid + c * 256;
        int row = chunk >> 3;
        int seg = chunk & 7;
        cp_async16(bs + swz(row, seg), gB + (size_t)row * (NA * 2) + seg * 16);
    }
    cp_commit();
    char* As = smem + (buf ? SP_A1 : SP_A0);
    int f = tid & 15, r0 = tid >> 4;
    #pragma unroll
    for (int i = 0; i < 4; ++i) {
        int row = r0 + 16 * i;
        float4 v = *(const float4*)(in + (size_t)(m0 + row) * PITCH + k0 + f * 4);
        __nv_bfloat162 h0 = __floats2bfloat162_rn(v.x, v.y);
        __nv_bfloat162 h1 = __floats2bfloat162_rn(v.z, v.w);
        *(uint2*)(As + swz(row, f >> 1) + (f & 1) * 8) =
            make_uint2(*(uint32_t*)&h0, *(uint32_t*)&h1);
    }
}

__global__ void __launch_bounds__(256, 1) support_mma(const float* __restrict__ in) {
    extern __shared__ char smem[];
    int tid = threadIdx.x;
    int wid = tid >> 5, lane = tid & 31;
    int m0 = blockIdx.x * 64;
    int warp_m = (wid & 1) * 32;
    int warp_n = (wid >> 1) * 64;

    int rowA[2], rowB[4];
    #pragma unroll
    for (int mi = 0; mi < 2; ++mi) rowA[mi] = warp_m + mi * 16 + (lane & 15);
    int hiA = lane >> 4;
    #pragma unroll
    for (int nb = 0; nb < 4; ++nb)
        rowB[nb] = warp_n + nb * 16 + ((lane >> 4) << 3) + (lane & 7);
    int hiB = (lane >> 3) & 1;

    float acc[2][8][4] = {};

    sp_load(in, smem, 0, 0, tid, m0);
    for (int it = 0; it < NA / 64; ++it) {
        int buf = it & 1;
        if (it + 1 < NA / 64) { sp_load(in, smem, buf ^ 1, (it + 1) * 64, tid, m0); cp_wait<1>(); }
        else cp_wait<0>();
        __syncthreads();
        uint32_t As = s2u(smem + (buf ? SP_A1 : SP_A0));
        uint32_t Bs = s2u(smem + (buf ? SP_B1 : SP_B0));
        #pragma unroll
        for (int kk = 0; kk < 4; ++kk) {
            uint32_t a[2][4];
            #pragma unroll
            for (int mi = 0; mi < 2; ++mi)
                ldsm4(a[mi], As + swz(rowA[mi], kk * 2 + hiA));
            #pragma unroll
            for (int nb = 0; nb < 4; ++nb) {
                uint32_t b[4];
                ldsm4(b, Bs + swz(rowB[nb], kk * 2 + hiB));
                mma16816(acc[0][2 * nb],     a[0], b[0], b[1]);
                mma16816(acc[0][2 * nb + 1], a[0], b[2], b[3]);
                mma16816(acc[1][2 * nb],     a[1], b[0], b[1]);
                mma16816(acc[1][2 * nb + 1], a[1], b[2], b[3]);
            }
        }
        __syncthreads();
    }

    int qr = lane >> 2, qc = (lane & 3) * 2;
    #pragma unroll
    for (int mi = 0; mi < 2; ++mi) {
        int j0 = warp_m + mi * 16 + qr;
        float dv0 = g_dinv[m0 + j0];
        float dv1 = g_dinv[m0 + j0 + 8];
        #pragma unroll
        for (int n8 = 0; n8 < 8; ++n8) {
            int n = warp_n + n8 * 8 + qc;
            *(__nv_bfloat16*)(smem + n * ST_PITCH + j0 * 2)             = __float2bfloat16(dv0 * acc[mi][n8][0]);
            *(__nv_bfloat16*)(smem + (n + 1) * ST_PITCH + j0 * 2)       = __float2bfloat16(dv0 * acc[mi][n8][1]);
            *(__nv_bfloat16*)(smem + n * ST_PITCH + (j0 + 8) * 2)       = __float2bfloat16(dv1 * acc[mi][n8][2]);
            *(__nv_bfloat16*)(smem + (n + 1) * ST_PITCH + (j0 + 8) * 2) = __float2bfloat16(dv1 * acc[mi][n8][3]);
        }
    }
    __syncthreads();
    #pragma unroll
    for (int c = 0; c < 8; ++c) {
        int chunk = tid + c * 256;
        int n = chunk >> 3;
        int seg = chunk & 7;
        uint4 v = *(const uint4*)(smem + n * ST_PITCH + seg * 16);
        *(uint4*)((char*)g_supT + ((size_t)n * NSMP + m0) * 2 + seg * 16) = v;
    }
}

// ---------------------------------------------------------------------------
// main (pure bf16 GEMM): out[:, :256] = diag(dinv) * bf16(A+I) @ S
// 128-thread CTAs (4 warps, warp tile 32x64), CTA 64x128, grid (128, 2),
// 3-stage cp.async ring (72KB smem) -> up to 3 CTAs/SM, barrier overlap.
// ---------------------------------------------------------------------------
#define MG7_STRIDE 24576   // per-stage: B(16KB) + A(8KB)
#define MG7_AOFF   16384
#define MG7_TOTAL  73728   // 3 stages
#define NIT        (NSMP / 64)

__device__ __forceinline__ void mg7_load(char* smem, int stage, int k0, int tid,
                                         int m0, int n0) {
    // B tile: 128 x 64 bf16 (1024 chunks, 8 per thread)
    uint32_t bs = s2u(smem + stage * MG7_STRIDE);
    const char* gB = (const char*)g_supT + (size_t)n0 * (NSMP * 2) + (size_t)k0 * 2;
    #pragma unroll
    for (int c = 0; c < 8; ++c) {
        int chunk = tid + c * 128;
        int row = chunk >> 3;
        int seg = chunk & 7;
        cp_async16(bs + swz(row, seg), gB + (size_t)row * (NSMP * 2) + seg * 16);
    }
    // A tile: 64 x 64 bf16 (512 chunks, 4 per thread)
    uint32_t as_ = s2u(smem + stage * MG7_STRIDE + MG7_AOFF);
    const char* gA = (const char*)g_Ab + (size_t)m0 * (NSMP * 2) + (size_t)k0 * 2;
    #pragma unroll
    for (int c = 0; c < 4; ++c) {
        int chunk = tid + c * 128;
        int row = chunk >> 3;
        int seg = chunk & 7;
        cp_async16(as_ + swz(row, seg), gA + (size_t)row * (NSMP * 2) + seg * 16);
    }
    cp_commit();
}

__global__ void __launch_bounds__(128, 3) main_gemm7(float* __restrict__ out) {
    extern __shared__ char smem[];
    int tid = threadIdx.x;
    int wid = tid >> 5, lane = tid & 31;
    int m0 = blockIdx.x * 64;
    int n0 = blockIdx.y * 128;
    int warp_m = (wid & 1) * 32;
    int warp_n = (wid >> 1) * 64;

    int rowA[2], rowB[4];
    #pragma unroll
    for (int mi = 0; mi < 2; ++mi) rowA[mi] = warp_m + mi * 16 + (lane & 15);
    int hiA = lane >> 4;
    #pragma unroll
    for (int nb = 0; nb < 4; ++nb)
        rowB[nb] = warp_n + nb * 16 + ((lane >> 4) << 3) + (lane & 7);
    int hiB = (lane >> 3) & 1;

    float acc[2][8][4] = {};

    mg7_load(smem, 0, 0, tid, m0, n0);
    mg7_load(smem, 1, 64, tid, m0, n0);

    for (int it = 0; it < NIT; ++it) {
        int stage = it % 3;
        if (it + 1 < NIT) cp_wait<1>(); else cp_wait<0>();
        __syncthreads();
        if (it + 2 < NIT) mg7_load(smem, (it + 2) % 3, (it + 2) * 64, tid, m0, n0);

        uint32_t Af = s2u(smem + stage * MG7_STRIDE + MG7_AOFF);
        uint32_t Bs = s2u(smem + stage * MG7_STRIDE);
        #pragma unroll
        for (int kk = 0; kk < 4; ++kk) {
            uint32_t a[2][4];
            #pragma unroll
            for (int mi = 0; mi < 2; ++mi)
                ldsm4(a[mi], Af + swz(rowA[mi], kk * 2 + hiA));
            #pragma unroll
            for (int nb = 0; nb < 4; ++nb) {
                uint32_t b[4];
                ldsm4(b, Bs + swz(rowB[nb], kk * 2 + hiB));
                mma16816(acc[0][2 * nb],     a[0], b[0], b[1]);
                mma16816(acc[0][2 * nb + 1], a[0], b[2], b[3]);
                mma16816(acc[1][2 * nb],     a[1], b[0], b[1]);
                mma16816(acc[1][2 * nb + 1], a[1], b[2], b[3]);
            }
        }
    }

    // epilogue: scale by dinv[row], store out[:, n0 + warp_n ...]
    int qr = lane >> 2, qc = (lane & 3) * 2;
    #pragma unroll
    for (int mi = 0; mi < 2; ++mi) {
        int r0g = m0 + warp_m + mi * 16 + qr;
        float dv0 = g_dinv[r0g];
        float dv1 = g_dinv[r0g + 8];
        float* o0 = out + (size_t)r0g * OPITCH + n0;
        float* o1 = o0 + (size_t)8 * OPITCH;
        #pragma unroll
        for (int n8 = 0; n8 < 8; ++n8) {
            int col = warp_n + n8 * 8 + qc;
            o0[col]     = dv0 * acc[mi][n8][0];
            o0[col + 1] = dv0 * acc[mi][n8][1];
            o1[col]     = dv1 * acc[mi][n8][2];
            o1[col + 1] = dv1 * acc[mi][n8][3];
        }
    }
}

// ---------------------------------------------------------------------------
extern "C" void kernel_launch(void* const* d_in, const int* in_sizes, int n_in,
                              void* d_out, int out_size) {
    const float* in = (const float*)d_in[0];
    const float* w  = (const float*)d_in[1];
    float* out = (float*)d_out;

    cudaFuncSetAttribute(support_mma, cudaFuncAttributeMaxDynamicSharedMemorySize, SP_TOTAL);
    cudaFuncSetAttribute(main_gemm7,  cudaFuncAttributeMaxDynamicSharedMemorySize, MG7_TOTAL);

    wt_kernel   <<<dim3(16, 8), 256>>>(w);
    colsum_fused<<<dim3(8, 64), 256>>>(in, out);
    finalize_d  <<<32, 256>>>();
    support_mma <<<128, 256, SP_TOTAL>>>(in);
    main_gemm7  <<<dim3(128, 2), 128, MG7_TOTAL>>>(out);
}